// round 1
// baseline (speedup 1.0000x reference)
#include <cuda_runtime.h>

#define NN 100000
#define DDIM 8
#define HDIM 256

// ---- scratch (static device globals; allocation-free) ----
__device__ float g_norm_src[NN];
__device__ float g_norm_dst[NN];
__device__ float g_md  [NN*DDIM];
__device__ float g_agg1[NN*DDIM];
__device__ float g_v   [NN*DDIM];
__device__ unsigned g_mask[NN*DDIM];   // 8 x 32-bit ballot words = 256 relu bits per node
__device__ float g_agg2[NN*DDIM];
__device__ float g_h2  [NN*DDIM];
__device__ float g_G   [NN*DDIM];
__device__ float g_r   [NN*DDIM];
__device__ float g_zz  [NN*DDIM];
__device__ float g_w   [NN*DDIM];
__device__ int   g_degout[NN];
__device__ int   g_degin [NN];

// ---- kernels ----
__global__ void k_zero(int n8, int n) {
    int i = blockIdx.x * blockDim.x + threadIdx.x;
    if (i < n8) {
        g_agg1[i] = 0.f; g_agg2[i] = 0.f; g_G[i] = 0.f; g_r[i] = 0.f; g_w[i] = 0.f;
    }
    if (i < n) { g_degout[i] = 0; g_degin[i] = 0; }
}

__global__ void k_deg(const int* __restrict__ src, const int* __restrict__ dst, int E) {
    int e = blockIdx.x * blockDim.x + threadIdx.x;
    if (e >= E) return;
    atomicAdd(&g_degout[src[e]], 1);
    atomicAdd(&g_degin [dst[e]], 1);
}

// norms, mass diagonal, dHdP = p / m_diag
__global__ void k_prep(const float* __restrict__ p, const float* __restrict__ M,
                       float* __restrict__ out, int n) {
    int i = blockIdx.x * blockDim.x + threadIdx.x;
    if (i >= n * DDIM) return;
    int nd = i >> 3, d = i & 7;
    float md = M[nd * 64 + d * 9];          // M[n,d,d]
    g_md[i] = md;
    out[nd * 16 + 8 + d] = p[i] / md;
    if (d == 0) {
        int od = g_degout[nd], id = g_degin[nd];
        g_norm_src[nd] = (od > 0) ? rsqrtf((float)od) : 1.0f;
        g_norm_dst[nd] = (id > 0) ? rsqrtf((float)id) : 1.0f;
    }
}

// agg1[dst] += q[src] * norm_src[src]    (8 threads per edge)
__global__ void k_agg1(const int* __restrict__ src, const int* __restrict__ dst,
                       const float* __restrict__ q, int E) {
    long long t = (long long)blockIdx.x * blockDim.x + threadIdx.x;
    if (t >= (long long)E * 8) return;
    int e = (int)(t >> 3), d = (int)(t & 7);
    int s = src[e], u = dst[e];
    atomicAdd(&g_agg2[0] - g_agg2 + &g_agg1[u * 8 + d], q[s * 8 + d] * g_norm_src[s]);
}

// forward node MLP: t1 = agg1*ndst ; u = t1@W1+b1 ; h = relu ; v = h@W2 ; store v, mask
__global__ void k_mlp_fwd(const float* __restrict__ W1v, const float* __restrict__ b1v,
                          const float* __restrict__ W2v, int n) {
    __shared__ float sW1[DDIM * HDIM];     // [d][j]
    __shared__ float sW2t[DDIM * HDIM];    // transposed: [d][j]
    __shared__ float sb1[HDIM];
    int tid = threadIdx.x;
    for (int i = tid; i < DDIM * HDIM; i += 256) {
        sW1[i] = W1v[i];
        int j = i >> 3, d = i & 7;
        sW2t[d * HDIM + j] = W2v[i];       // W2 [256,8] row-major
    }
    sb1[tid] = b1v[tid];
    __syncthreads();
    int warp = tid >> 5, lane = tid & 31;
    int node = blockIdx.x * 8 + warp;
    if (node >= n) return;
    float ndst = g_norm_dst[node];
    float t1[8];
#pragma unroll
    for (int d = 0; d < 8; d++) t1[d] = g_agg1[node * 8 + d] * ndst;
    float acc[8] = {0.f,0.f,0.f,0.f,0.f,0.f,0.f,0.f};
#pragma unroll
    for (int k = 0; k < 8; k++) {
        int j = k * 32 + lane;
        float u = sb1[j];
#pragma unroll
        for (int d = 0; d < 8; d++) u = fmaf(t1[d], sW1[d * HDIM + j], u);
        unsigned m = __ballot_sync(0xFFFFFFFFu, u > 0.f);
        if (lane == 0) g_mask[node * 8 + k] = m;
        float h = (u > 0.f) ? u : 0.f;
#pragma unroll
        for (int d = 0; d < 8; d++) acc[d] = fmaf(h, sW2t[d * HDIM + j], acc[d]);
    }
#pragma unroll
    for (int off = 16; off; off >>= 1)
#pragma unroll
        for (int d = 0; d < 8; d++) acc[d] += __shfl_xor_sync(0xFFFFFFFFu, acc[d], off);
    if (lane == 0) {
#pragma unroll
        for (int d = 0; d < 8; d++) g_v[node * 8 + d] = acc[d];
    }
}

// agg2[dst] += v[src] * norm_src[src]
__global__ void k_agg2(const int* __restrict__ src, const int* __restrict__ dst, int E) {
    long long t = (long long)blockIdx.x * blockDim.x + threadIdx.x;
    if (t >= (long long)E * 8) return;
    int e = (int)(t >> 3), d = (int)(t & 7);
    int s = src[e], u = dst[e];
    atomicAdd(&g_agg2[u * 8 + d], g_v[s * 8 + d] * g_norm_src[s]);
}

// h2 = agg2*ndst + b2 + q
__global__ void k_h2(const float* __restrict__ q, const float* __restrict__ b2, int n) {
    int i = blockIdx.x * blockDim.x + threadIdx.x;
    if (i >= n * DDIM) return;
    int nd = i >> 3, d = i & 7;
    g_h2[i] = g_agg2[i] * g_norm_dst[nd] + b2[d] + q[i];
}

// per-edge force: c = 0.5*g*s/||delta||^3 ; G[src]-=c*delta ; G[dst]+=c*delta
__global__ void k_force(const int* __restrict__ src, const int* __restrict__ dst,
                        const float* __restrict__ grav, int E) {
    long long t = (long long)blockIdx.x * blockDim.x + threadIdx.x;
    if (t >= (long long)E * 8) return;
    unsigned amask = __activemask();
    int e = (int)(t >> 3), d = (int)(t & 7);
    int s = src[e], u = dst[e];
    float dd = g_h2[s * 8 + d] - g_h2[u * 8 + d];
    float ms = g_md[s * 8 + d] * g_md[u * 8 + d];
    float e2 = dd * dd, sm = ms;
#pragma unroll
    for (int off = 1; off < 8; off <<= 1) {
        e2 += __shfl_xor_sync(amask, e2, off);
        sm += __shfl_xor_sync(amask, sm, off);
    }
    float inv = rsqrtf(e2);
    float c = 0.5f * grav[0] * sm * inv * inv * inv;
    float f = c * dd;
    atomicAdd(&g_G[s * 8 + d], -f);
    atomicAdd(&g_G[u * 8 + d],  f);
}

// r[src] += G[dst]*norm_dst[dst]   (A^T of G, norm_src applied later)
__global__ void k_aggR(const int* __restrict__ src, const int* __restrict__ dst, int E) {
    long long t = (long long)blockIdx.x * blockDim.x + threadIdx.x;
    if (t >= (long long)E * 8) return;
    int e = (int)(t >> 3), d = (int)(t & 7);
    int s = src[e], u = dst[e];
    atomicAdd(&g_r[s * 8 + d], g_G[u * 8 + d] * g_norm_dst[u]);
}

// backward node MLP: zz = ((r*nsrc)@W2^T ⊙ mask) @ W1^T
__global__ void k_mlp_bwd(const float* __restrict__ W1v, const float* __restrict__ W2v, int n) {
    __shared__ float sW1[DDIM * HDIM];     // [d][j]
    __shared__ float sW2t[DDIM * HDIM];    // [d][j]
    int tid = threadIdx.x;
    for (int i = tid; i < DDIM * HDIM; i += 256) {
        sW1[i] = W1v[i];
        int j = i >> 3, d = i & 7;
        sW2t[d * HDIM + j] = W2v[i];
    }
    __syncthreads();
    int warp = tid >> 5, lane = tid & 31;
    int node = blockIdx.x * 8 + warp;
    if (node >= n) return;
    float nsrc = g_norm_src[node];
    float rr[8];
#pragma unroll
    for (int d = 0; d < 8; d++) rr[d] = g_r[node * 8 + d] * nsrc;
    float acc[8] = {0.f,0.f,0.f,0.f,0.f,0.f,0.f,0.f};
#pragma unroll
    for (int k = 0; k < 8; k++) {
        int j = k * 32 + lane;
        float gh = 0.f;
#pragma unroll
        for (int d = 0; d < 8; d++) gh = fmaf(rr[d], sW2t[d * HDIM + j], gh);
        unsigned m = g_mask[node * 8 + k];
        float gu = ((m >> lane) & 1u) ? gh : 0.f;
#pragma unroll
        for (int d = 0; d < 8; d++) acc[d] = fmaf(gu, sW1[d * HDIM + j], acc[d]);
    }
#pragma unroll
    for (int off = 16; off; off >>= 1)
#pragma unroll
        for (int d = 0; d < 8; d++) acc[d] += __shfl_xor_sync(0xFFFFFFFFu, acc[d], off);
    if (lane == 0) {
#pragma unroll
        for (int d = 0; d < 8; d++) g_zz[node * 8 + d] = acc[d];
    }
}

// w[src] += zz[dst]*norm_dst[dst]
__global__ void k_aggZ(const int* __restrict__ src, const int* __restrict__ dst, int E) {
    long long t = (long long)blockIdx.x * blockDim.x + threadIdx.x;
    if (t >= (long long)E * 8) return;
    int e = (int)(t >> 3), d = (int)(t & 7);
    int s = src[e], u = dst[e];
    atomicAdd(&g_w[s * 8 + d], g_zz[u * 8 + d] * g_norm_dst[u]);
}

// dHdQ = G + norm_src * w
__global__ void k_final(float* __restrict__ out, int n) {
    int i = blockIdx.x * blockDim.x + threadIdx.x;
    if (i >= n * DDIM) return;
    int nd = i >> 3, d = i & 7;
    out[nd * 16 + d] = g_G[i] + g_norm_src[nd] * g_w[i];
}

extern "C" void kernel_launch(void* const* d_in, const int* in_sizes, int n_in,
                              void* d_out, int out_size) {
    const float* q    = (const float*)d_in[0];
    const float* p    = (const float*)d_in[1];
    const float* M    = (const float*)d_in[2];
    const int*   src  = (const int*)  d_in[3];
    const int*   dst  = (const int*)  d_in[4];
    const float* W1   = (const float*)d_in[5];
    const float* b1   = (const float*)d_in[6];
    const float* W2   = (const float*)d_in[7];
    const float* b2   = (const float*)d_in[8];
    const float* grav = (const float*)d_in[9];
    float* out = (float*)d_out;

    int N = in_sizes[0] / DDIM;
    int E = in_sizes[3];
    if (N > NN) return;

    int n8 = N * 8;
    long long e8 = (long long)E * 8;
    int gN8 = (n8 + 255) / 256;
    int gE  = (E + 255) / 256;
    int gE8 = (int)((e8 + 255) / 256);
    int gW  = (N + 7) / 8;

    k_zero   <<<gN8, 256>>>(n8, N);
    k_deg    <<<gE,  256>>>(src, dst, E);
    k_prep   <<<gN8, 256>>>(p, M, out, N);
    k_agg1   <<<gE8, 256>>>(src, dst, q, E);
    k_mlp_fwd<<<gW,  256>>>(W1, b1, W2, N);
    k_agg2   <<<gE8, 256>>>(src, dst, E);
    k_h2     <<<gN8, 256>>>(q, b2, N);
    k_force  <<<gE8, 256>>>(src, dst, grav, E);
    k_aggR   <<<gE8, 256>>>(src, dst, E);
    k_mlp_bwd<<<gW,  256>>>(W1, W2, N);
    k_aggZ   <<<gE8, 256>>>(src, dst, E);
    k_final  <<<gN8, 256>>>(out, N);
}

// round 3
// speedup vs baseline: 1.0947x; 1.0947x over previous
#include <cuda_runtime.h>

#define NN 100000
#define DDIM 8
#define HDIM 256

// ---- scratch (float4-typed for 16B alignment of RED.128) ----
__device__ float4 g_qn  [NN*2];   // q * norm_src
__device__ float4 g_md4 [NN*2];   // mass diagonal
__device__ float4 g_agg1[NN*2];
__device__ float4 g_vn  [NN*2];   // v * norm_src
__device__ float4 g_agg2[NN*2];
__device__ float4 g_h2  [NN*2];
__device__ float4 g_G   [NN*2];
__device__ float4 g_Gn  [NN*2];   // G * norm_dst
__device__ float4 g_r   [NN*2];
__device__ float4 g_zzn [NN*2];   // zz * norm_dst
__device__ float4 g_w   [NN*2];
__device__ float  g_norm_src[NN];
__device__ float  g_norm_dst[NN];
__device__ unsigned g_mask[NN*DDIM];
__device__ int    g_degout[NN];
__device__ int    g_degin [NN];

__device__ __forceinline__ void red_add_v4(float4* addr, float4 v) {
    asm volatile("red.global.add.v4.f32 [%0], {%1, %2, %3, %4};"
                 :: "l"(addr), "f"(v.x), "f"(v.y), "f"(v.z), "f"(v.w) : "memory");
}
__device__ __forceinline__ float4 f4add(float4 a, float4 b) {
    return make_float4(a.x+b.x, a.y+b.y, a.z+b.z, a.w+b.w);
}
__device__ __forceinline__ float4 f4scale(float4 a, float s) {
    return make_float4(a.x*s, a.y*s, a.z*s, a.w*s);
}

// zero accumulators + degree counters
__global__ void k_zero(int n4, int n) {
    int i = blockIdx.x * blockDim.x + threadIdx.x;
    float4 z = make_float4(0.f, 0.f, 0.f, 0.f);
    if (i < n4) { g_agg1[i] = z; g_agg2[i] = z; g_G[i] = z; g_r[i] = z; g_w[i] = z; }
    if (i < n)  { g_degout[i] = 0; g_degin[i] = 0; }
}

__global__ void k_deg(const int* __restrict__ src, const int* __restrict__ dst, int E) {
    int e = blockIdx.x * blockDim.x + threadIdx.x;
    if (e >= E) return;
    atomicAdd(&g_degout[src[e]], 1);
    atomicAdd(&g_degin [dst[e]], 1);
}

// per node: norms, mass diag, dHdP = p/md, qn = q*nsrc
__global__ void k_prep(const float* __restrict__ p, const float* __restrict__ M,
                       const float* __restrict__ q, float4* __restrict__ out4, int n) {
    int nd = blockIdx.x * blockDim.x + threadIdx.x;
    if (nd >= n) return;
    int od = g_degout[nd], id = g_degin[nd];
    float nsrc = (od > 0) ? rsqrtf((float)od) : 1.0f;
    float ndst = (id > 0) ? rsqrtf((float)id) : 1.0f;
    g_norm_src[nd] = nsrc;
    g_norm_dst[nd] = ndst;
    const float* Mr = M + (long long)nd * 64;
    float md[8];
#pragma unroll
    for (int d = 0; d < 8; d++) md[d] = Mr[d * 9];
    g_md4[nd*2]   = make_float4(md[0], md[1], md[2], md[3]);
    g_md4[nd*2+1] = make_float4(md[4], md[5], md[6], md[7]);
    const float4* q4 = (const float4*)q;
    const float4* p4 = (const float4*)p;
    g_qn[nd*2]   = f4scale(q4[nd*2],   nsrc);
    g_qn[nd*2+1] = f4scale(q4[nd*2+1], nsrc);
    float4 pa = p4[nd*2], pb = p4[nd*2+1];
    out4[nd*4+2] = make_float4(pa.x/md[0], pa.y/md[1], pa.z/md[2], pa.w/md[3]);
    out4[nd*4+3] = make_float4(pb.x/md[4], pb.y/md[5], pb.z/md[6], pb.w/md[7]);
}

// ---- edge aggregations: device globals referenced DIRECTLY (no host-passed symbols) ----
// agg1[u] += qn[s]
__global__ void k_aggQ(const int* __restrict__ src, const int* __restrict__ dst, int E) {
    int e = blockIdx.x * blockDim.x + threadIdx.x;
    if (e >= E) return;
    int s = src[e], u = dst[e];
    red_add_v4(&g_agg1[u*2],   __ldg(&g_qn[s*2]));
    red_add_v4(&g_agg1[u*2+1], __ldg(&g_qn[s*2+1]));
}
// agg2[u] += vn[s]
__global__ void k_aggV(const int* __restrict__ src, const int* __restrict__ dst, int E) {
    int e = blockIdx.x * blockDim.x + threadIdx.x;
    if (e >= E) return;
    int s = src[e], u = dst[e];
    red_add_v4(&g_agg2[u*2],   __ldg(&g_vn[s*2]));
    red_add_v4(&g_agg2[u*2+1], __ldg(&g_vn[s*2+1]));
}
// r[s] += Gn[u]
__global__ void k_aggR(const int* __restrict__ src, const int* __restrict__ dst, int E) {
    int e = blockIdx.x * blockDim.x + threadIdx.x;
    if (e >= E) return;
    int s = src[e], u = dst[e];
    red_add_v4(&g_r[s*2],   __ldg(&g_Gn[u*2]));
    red_add_v4(&g_r[s*2+1], __ldg(&g_Gn[u*2+1]));
}
// w[s] += zzn[u]
__global__ void k_aggW(const int* __restrict__ src, const int* __restrict__ dst, int E) {
    int e = blockIdx.x * blockDim.x + threadIdx.x;
    if (e >= E) return;
    int s = src[e], u = dst[e];
    red_add_v4(&g_w[s*2],   __ldg(&g_zzn[u*2]));
    red_add_v4(&g_w[s*2+1], __ldg(&g_zzn[u*2+1]));
}

// forward node MLP
__global__ void k_mlp_fwd(const float* __restrict__ W1v, const float* __restrict__ b1v,
                          const float* __restrict__ W2v, int n) {
    __shared__ float sW1[DDIM * HDIM];     // [d][j]
    __shared__ float sW2t[DDIM * HDIM];    // [d][j]
    __shared__ float sb1[HDIM];
    int tid = threadIdx.x;
    for (int i = tid; i < DDIM * HDIM; i += 256) {
        sW1[i] = W1v[i];
        int j = i >> 3, d = i & 7;
        sW2t[d * HDIM + j] = W2v[i];
    }
    sb1[tid] = b1v[tid];
    __syncthreads();
    int warp = tid >> 5, lane = tid & 31;
    int node = blockIdx.x * 8 + warp;
    if (node >= n) return;
    float ndst = g_norm_dst[node];
    const float* a1 = (const float*)&g_agg1[node*2];
    float t1[8];
#pragma unroll
    for (int d = 0; d < 8; d++) t1[d] = a1[d] * ndst;
    float acc[8] = {0.f,0.f,0.f,0.f,0.f,0.f,0.f,0.f};
#pragma unroll
    for (int k = 0; k < 8; k++) {
        int j = k * 32 + lane;
        float u = sb1[j];
#pragma unroll
        for (int d = 0; d < 8; d++) u = fmaf(t1[d], sW1[d * HDIM + j], u);
        unsigned m = __ballot_sync(0xFFFFFFFFu, u > 0.f);
        if (lane == 0) g_mask[node * 8 + k] = m;
        float h = (u > 0.f) ? u : 0.f;
#pragma unroll
        for (int d = 0; d < 8; d++) acc[d] = fmaf(h, sW2t[d * HDIM + j], acc[d]);
    }
#pragma unroll
    for (int off = 16; off; off >>= 1)
#pragma unroll
        for (int d = 0; d < 8; d++) acc[d] += __shfl_xor_sync(0xFFFFFFFFu, acc[d], off);
    if (lane == 0) {
        float ns = g_norm_src[node];
        g_vn[node*2]   = make_float4(acc[0]*ns, acc[1]*ns, acc[2]*ns, acc[3]*ns);
        g_vn[node*2+1] = make_float4(acc[4]*ns, acc[5]*ns, acc[6]*ns, acc[7]*ns);
    }
}

// h2 = agg2*ndst + b2 + q
__global__ void k_h2(const float* __restrict__ q, const float* __restrict__ b2, int n) {
    int i = blockIdx.x * blockDim.x + threadIdx.x;
    if (i >= n * 2) return;
    int nd = i >> 1;
    float ndst = g_norm_dst[nd];
    const float4* q4 = (const float4*)q;
    const float4* b24 = (const float4*)b2;
    g_h2[i] = f4add(f4add(f4scale(g_agg2[i], ndst), b24[i & 1]), q4[i]);
}

// per-edge force
__global__ void k_force(const int* __restrict__ src, const int* __restrict__ dst,
                        const float* __restrict__ grav, int E) {
    int e = blockIdx.x * blockDim.x + threadIdx.x;
    if (e >= E) return;
    int s = src[e], u = dst[e];
    float4 hsa = __ldg(&g_h2[s*2]), hsb = __ldg(&g_h2[s*2+1]);
    float4 hua = __ldg(&g_h2[u*2]), hub = __ldg(&g_h2[u*2+1]);
    float4 msa = __ldg(&g_md4[s*2]), msb = __ldg(&g_md4[s*2+1]);
    float4 mua = __ldg(&g_md4[u*2]), mub = __ldg(&g_md4[u*2+1]);
    float4 da = make_float4(hsa.x-hua.x, hsa.y-hua.y, hsa.z-hua.z, hsa.w-hua.w);
    float4 db = make_float4(hsb.x-hub.x, hsb.y-hub.y, hsb.z-hub.z, hsb.w-hub.w);
    float e2 = da.x*da.x + da.y*da.y + da.z*da.z + da.w*da.w
             + db.x*db.x + db.y*db.y + db.z*db.z + db.w*db.w;
    float sm = msa.x*mua.x + msa.y*mua.y + msa.z*mua.z + msa.w*mua.w
             + msb.x*mub.x + msb.y*mub.y + msb.z*mub.z + msb.w*mub.w;
    float inv = rsqrtf(e2);
    float c = 0.5f * __ldg(grav) * sm * inv * inv * inv;
    float4 fa = f4scale(da, c), fb = f4scale(db, c);
    red_add_v4(&g_G[u*2],   fa);
    red_add_v4(&g_G[u*2+1], fb);
    red_add_v4(&g_G[s*2],   make_float4(-fa.x, -fa.y, -fa.z, -fa.w));
    red_add_v4(&g_G[s*2+1], make_float4(-fb.x, -fb.y, -fb.z, -fb.w));
}

// Gn = G * ndst
__global__ void k_scaleG(int n) {
    int i = blockIdx.x * blockDim.x + threadIdx.x;
    if (i >= n * 2) return;
    g_Gn[i] = f4scale(g_G[i], g_norm_dst[i >> 1]);
}

// backward node MLP
__global__ void k_mlp_bwd(const float* __restrict__ W1v, const float* __restrict__ W2v, int n) {
    __shared__ float sW1[DDIM * HDIM];
    __shared__ float sW2t[DDIM * HDIM];
    int tid = threadIdx.x;
    for (int i = tid; i < DDIM * HDIM; i += 256) {
        sW1[i] = W1v[i];
        int j = i >> 3, d = i & 7;
        sW2t[d * HDIM + j] = W2v[i];
    }
    __syncthreads();
    int warp = tid >> 5, lane = tid & 31;
    int node = blockIdx.x * 8 + warp;
    if (node >= n) return;
    float nsrc = g_norm_src[node];
    const float* rv = (const float*)&g_r[node*2];
    float rr[8];
#pragma unroll
    for (int d = 0; d < 8; d++) rr[d] = rv[d] * nsrc;
    float acc[8] = {0.f,0.f,0.f,0.f,0.f,0.f,0.f,0.f};
#pragma unroll
    for (int k = 0; k < 8; k++) {
        int j = k * 32 + lane;
        float gh = 0.f;
#pragma unroll
        for (int d = 0; d < 8; d++) gh = fmaf(rr[d], sW2t[d * HDIM + j], gh);
        unsigned m = g_mask[node * 8 + k];
        float gu = ((m >> lane) & 1u) ? gh : 0.f;
#pragma unroll
        for (int d = 0; d < 8; d++) acc[d] = fmaf(gu, sW1[d * HDIM + j], acc[d]);
    }
#pragma unroll
    for (int off = 16; off; off >>= 1)
#pragma unroll
        for (int d = 0; d < 8; d++) acc[d] += __shfl_xor_sync(0xFFFFFFFFu, acc[d], off);
    if (lane == 0) {
        float ndst = g_norm_dst[node];
        g_zzn[node*2]   = make_float4(acc[0]*ndst, acc[1]*ndst, acc[2]*ndst, acc[3]*ndst);
        g_zzn[node*2+1] = make_float4(acc[4]*ndst, acc[5]*ndst, acc[6]*ndst, acc[7]*ndst);
    }
}

// out.dHdQ = G + nsrc * w
__global__ void k_final(float4* __restrict__ out4, int n) {
    int i = blockIdx.x * blockDim.x + threadIdx.x;
    if (i >= n * 2) return;
    int nd = i >> 1;
    float ns = g_norm_src[nd];
    out4[nd*4 + (i & 1)] = f4add(g_G[i], f4scale(g_w[i], ns));
}

extern "C" void kernel_launch(void* const* d_in, const int* in_sizes, int n_in,
                              void* d_out, int out_size) {
    const float* q    = (const float*)d_in[0];
    const float* p    = (const float*)d_in[1];
    const float* M    = (const float*)d_in[2];
    const int*   src  = (const int*)  d_in[3];
    const int*   dst  = (const int*)  d_in[4];
    const float* W1   = (const float*)d_in[5];
    const float* b1   = (const float*)d_in[6];
    const float* W2   = (const float*)d_in[7];
    const float* b2   = (const float*)d_in[8];
    const float* grav = (const float*)d_in[9];
    float4* out4 = (float4*)d_out;

    int N = in_sizes[0] / DDIM;
    int E = in_sizes[3];
    if (N > NN) return;

    int n4 = N * 2;
    int gN4 = (n4 + 255) / 256;
    int gN  = (N + 255) / 256;
    int gE  = (E + 255) / 256;
    int gW  = (N + 7) / 8;

    k_zero   <<<gN4, 256>>>(n4, N);
    k_deg    <<<gE,  256>>>(src, dst, E);
    k_prep   <<<gN,  256>>>(p, M, q, out4, N);
    k_aggQ   <<<gE,  256>>>(src, dst, E);
    k_mlp_fwd<<<gW,  256>>>(W1, b1, W2, N);
    k_aggV   <<<gE,  256>>>(src, dst, E);
    k_h2     <<<gN4, 256>>>(q, b2, N);
    k_force  <<<gE,  256>>>(src, dst, grav, E);
    k_scaleG <<<gN4, 256>>>(N);
    k_aggR   <<<gE,  256>>>(src, dst, E);
    k_mlp_bwd<<<gW,  256>>>(W1, W2, N);
    k_aggW   <<<gE,  256>>>(src, dst, E);
    k_final  <<<gN4, 256>>>(out4, N);
}